// round 1
// baseline (speedup 1.0000x reference)
#include <cuda_runtime.h>
#include <cstdint>

// ---------------------------------------------------------------------------
// GAT, 2 layers. N=4096, F=512, H1=8, D1=8 (64 hidden), C=16.
// Inputs (metadata order):
//   0: node_matrix (4096,512) f32
//   1: adj_matrix  (4096,4096) bool (layout auto-detected: bool8 / i32 / f32)
//   2: W1 (512,8,8)=(512,64) f32
//   3: a1_src (8,8) f32     4: a1_dst (8,8) f32
//   5: W2 (64,1,16)=(64,16) f32
//   6: a2_src (1,16) f32    7: a2_dst (1,16) f32
// Output: z2 (4096,16) f32
// ---------------------------------------------------------------------------

#define N_NODES 4096
#define F_IN    512
#define HD1     64      // 8 heads x 8 dims
#define NH1     8
#define D1      8
#define C2      16
#define MAXDEG  256

// ---- scratch (static device globals; no allocation) ----
__device__ int   g_nbr[N_NODES * MAXDEG];
__device__ int   g_deg[N_NODES];
__device__ float g_h1 [N_NODES * HD1];
__device__ float g_es1[N_NODES * NH1];
__device__ float g_ed1[N_NODES * NH1];
__device__ float g_a1 [N_NODES * HD1];
__device__ float g_h2 [N_NODES * C2];
__device__ float g_es2[N_NODES];
__device__ float g_ed2[N_NODES];

// ---------------------------------------------------------------------------
// K1: build per-row neighbor lists (deterministic, sorted). 1 block per row.
// 128 threads, each owns 32 consecutive columns; block prefix-scan for offsets.
// ---------------------------------------------------------------------------
__global__ __launch_bounds__(128) void k_build_nbr(const void* __restrict__ adj)
{
    const int i   = blockIdx.x;
    const int tid = threadIdx.x;
    const uint8_t* u8 = (const uint8_t*)adj;

    // Layout detection via self-loop adj[1][1]==1:
    //   bool8 : byte[1*4096+1]            == 1
    //   int32 : byte[4*(1*4096+1)]        == 1
    //   float : else (1.0f => byte3==0x3F)
    int fmt;  // 0=bool8, 1=i32, 2=f32
    if (u8[(size_t)N_NODES + 1] == 1)               fmt = 0;
    else if (u8[4 * ((size_t)N_NODES + 1)] == 1)    fmt = 1;
    else                                            fmt = 2;

    const int c0 = tid * 32;          // 128 threads * 32 cols = 4096
    int cnt = 0;

    const uint8_t* rb = u8 + (size_t)i * N_NODES;
    const int*     ri = (const int*)adj   + (size_t)i * N_NODES;
    const float*   rf = (const float*)adj + (size_t)i * N_NODES;

    #pragma unroll 4
    for (int k = 0; k < 32; k++) {
        int c = c0 + k;
        bool p;
        if (fmt == 0)      p = (rb[c] != 0);
        else if (fmt == 1) p = (ri[c] != 0);
        else               p = (rf[c] != 0.0f);
        cnt += p ? 1 : 0;
    }

    __shared__ int s_cnt[128];
    __shared__ int s_off[129];
    s_cnt[tid] = cnt;
    __syncthreads();
    if (tid == 0) {
        int run = 0;
        for (int t = 0; t < 128; t++) { s_off[t] = run; run += s_cnt[t]; }
        s_off[128] = run;
        g_deg[i] = (run > MAXDEG) ? MAXDEG : run;
    }
    __syncthreads();

    int base = s_off[tid];
    int* out = g_nbr + (size_t)i * MAXDEG;
    #pragma unroll 4
    for (int k = 0; k < 32; k++) {
        int c = c0 + k;
        bool p;
        if (fmt == 0)      p = (rb[c] != 0);
        else if (fmt == 1) p = (ri[c] != 0);
        else               p = (rf[c] != 0.0f);
        if (p) { if (base < MAXDEG) out[base] = c; base++; }
    }
}

// ---------------------------------------------------------------------------
// K2: GEMM1  h1 = x @ W1   (4096x512 * 512x64). 64 blocks, 256 thr, 4x4/thread.
// ---------------------------------------------------------------------------
__global__ __launch_bounds__(256) void k_gemm1(const float* __restrict__ X,
                                               const float* __restrict__ W)
{
    __shared__ float As[32][64];  // [k][m]
    __shared__ float Bs[32][64];  // [k][n]

    const int tid = threadIdx.x;
    const int tx  = tid & 15;     // n-group
    const int ty  = tid >> 4;     // m-group
    const int m0  = blockIdx.x * 64;

    float acc[4][4] = {};

    for (int kt = 0; kt < F_IN; kt += 32) {
        // A tile: 64 rows x 32 cols = 512 float4
        #pragma unroll
        for (int it = 0; it < 2; it++) {
            int id = tid + it * 256;
            int r  = id >> 3;          // 8 float4 per row
            int c4 = id & 7;
            float4 v = *(const float4*)(X + (size_t)(m0 + r) * F_IN + kt + c4 * 4);
            As[c4 * 4 + 0][r] = v.x;
            As[c4 * 4 + 1][r] = v.y;
            As[c4 * 4 + 2][r] = v.z;
            As[c4 * 4 + 3][r] = v.w;
        }
        // B tile: 32 rows x 64 cols = 512 float4
        #pragma unroll
        for (int it = 0; it < 2; it++) {
            int id = tid + it * 256;
            int r  = id >> 4;          // 16 float4 per row
            int c4 = id & 15;
            *(float4*)(&Bs[r][c4 * 4]) =
                *(const float4*)(W + (size_t)(kt + r) * HD1 + c4 * 4);
        }
        __syncthreads();
        #pragma unroll
        for (int k = 0; k < 32; k++) {
            float a[4], b[4];
            #pragma unroll
            for (int u = 0; u < 4; u++) a[u] = As[k][ty * 4 + u];
            #pragma unroll
            for (int u = 0; u < 4; u++) b[u] = Bs[k][tx * 4 + u];
            #pragma unroll
            for (int u = 0; u < 4; u++)
                #pragma unroll
                for (int v = 0; v < 4; v++)
                    acc[u][v] += a[u] * b[v];
        }
        __syncthreads();
    }
    #pragma unroll
    for (int u = 0; u < 4; u++)
        #pragma unroll
        for (int v = 0; v < 4; v++)
            g_h1[(size_t)(m0 + ty * 4 + u) * HD1 + tx * 4 + v] = acc[u][v];
}

// ---------------------------------------------------------------------------
// K2b: es1/ed1 scores.  1 thread per (n,h).
// ---------------------------------------------------------------------------
__global__ __launch_bounds__(256) void k_scores1(const float* __restrict__ a_src,
                                                 const float* __restrict__ a_dst)
{
    int idx = blockIdx.x * blockDim.x + threadIdx.x;   // n*8+h
    if (idx >= N_NODES * NH1) return;
    int h = idx & (NH1 - 1);
    const float* hp = g_h1 + (size_t)(idx >> 3) * HD1 + h * D1;
    float s = 0.f, d = 0.f;
    #pragma unroll
    for (int k = 0; k < D1; k++) {
        s += hp[k] * a_src[h * D1 + k];
        d += hp[k] * a_dst[h * D1 + k];
    }
    g_es1[idx] = s;
    g_ed1[idx] = d;
}

// ---------------------------------------------------------------------------
// K3: layer-1 sparse attention + ELU. 1 block per row, 128 threads.
// ---------------------------------------------------------------------------
__global__ __launch_bounds__(128) void k_attn1()
{
    const int i   = blockIdx.x;
    const int tid = threadIdx.x;
    const int deg = g_deg[i];

    __shared__ int   snbr[MAXDEG];
    __shared__ float ew[MAXDEG * NH1];
    __shared__ float sm[NH1], ss[NH1];

    for (int j = tid; j < deg; j += 128)
        snbr[j] = g_nbr[(size_t)i * MAXDEG + j];
    __syncthreads();

    const int tot = deg * NH1;
    for (int idx = tid; idx < tot; idx += 128) {
        int j = idx >> 3, h = idx & 7;
        float e = g_es1[i * NH1 + h] + g_ed1[snbr[j] * NH1 + h];
        e = (e > 0.f) ? e : 0.2f * e;
        ew[idx] = e;
    }
    __syncthreads();

    if (tid < NH1) {
        float m = -1e30f;
        for (int j = 0; j < deg; j++) m = fmaxf(m, ew[j * NH1 + tid]);
        float s = 0.f;
        for (int j = 0; j < deg; j++) s += __expf(ew[j * NH1 + tid] - m);
        sm[tid] = m;
        ss[tid] = 1.f / s;
    }
    __syncthreads();

    for (int idx = tid; idx < tot; idx += 128) {
        int h = idx & 7;
        ew[idx] = __expf(ew[idx] - sm[h]) * ss[h];
    }
    __syncthreads();

    if (tid < HD1) {
        const int h = tid >> 3;
        float acc = 0.f;
        for (int j = 0; j < deg; j++)
            acc += ew[j * NH1 + h] * g_h1[(size_t)snbr[j] * HD1 + tid];
        // ELU (alpha=1)
        acc = (acc > 0.f) ? acc : expm1f(acc);
        g_a1[(size_t)i * HD1 + tid] = acc;
    }
}

// ---------------------------------------------------------------------------
// K4: GEMM2  h2 = a1 @ W2  (4096x64 * 64x16). 256 blocks x 256 thr.
// ---------------------------------------------------------------------------
__global__ __launch_bounds__(256) void k_gemm2(const float* __restrict__ W2)
{
    __shared__ float sW[HD1 * C2];     // 1024
    __shared__ float sA[16 * HD1];     // 16 rows x 64

    const int tid = threadIdx.x;
    const int n0  = blockIdx.x * 16;

    {   // load W2 (1024 floats = 256 float4)
        float4 v = *(const float4*)(W2 + tid * 4);
        *(float4*)(&sW[tid * 4]) = v;
    }
    {   // load 16 rows of a1
        int r  = tid >> 4;       // 16 float4 per row
        int c4 = tid & 15;
        *(float4*)(&sA[r * HD1 + c4 * 4]) =
            *(const float4*)(g_a1 + (size_t)(n0 + r) * HD1 + c4 * 4);
    }
    __syncthreads();

    const int rloc = tid >> 4;   // 0..15
    const int c    = tid & 15;
    float acc = 0.f;
    #pragma unroll
    for (int k = 0; k < HD1; k++)
        acc += sA[rloc * HD1 + k] * sW[k * C2 + c];
    g_h2[(size_t)(n0 + rloc) * C2 + c] = acc;
}

// K4b: es2/ed2, 1 thread per node
__global__ __launch_bounds__(256) void k_scores2(const float* __restrict__ a_src,
                                                 const float* __restrict__ a_dst)
{
    int n = blockIdx.x * blockDim.x + threadIdx.x;
    if (n >= N_NODES) return;
    const float* hp = g_h2 + (size_t)n * C2;
    float s = 0.f, d = 0.f;
    #pragma unroll
    for (int k = 0; k < C2; k++) {
        s += hp[k] * a_src[k];
        d += hp[k] * a_dst[k];
    }
    g_es2[n] = s;
    g_ed2[n] = d;
}

// ---------------------------------------------------------------------------
// K5: layer-2 sparse attention (single head, D=16). 1 block per row, 64 thr.
// ---------------------------------------------------------------------------
__global__ __launch_bounds__(64) void k_attn2(float* __restrict__ out)
{
    const int i   = blockIdx.x;
    const int tid = threadIdx.x;
    const int deg = g_deg[i];

    __shared__ int   snbr[MAXDEG];
    __shared__ float ew[MAXDEG];
    __shared__ float sm, ss;

    for (int j = tid; j < deg; j += 64)
        snbr[j] = g_nbr[(size_t)i * MAXDEG + j];
    __syncthreads();

    const float esi = g_es2[i];
    for (int j = tid; j < deg; j += 64) {
        float e = esi + g_ed2[snbr[j]];
        e = (e > 0.f) ? e : 0.2f * e;
        ew[j] = e;
    }
    __syncthreads();

    if (tid == 0) {
        float m = -1e30f;
        for (int j = 0; j < deg; j++) m = fmaxf(m, ew[j]);
        float s = 0.f;
        for (int j = 0; j < deg; j++) s += __expf(ew[j] - m);
        sm = m;
        ss = 1.f / s;
    }
    __syncthreads();

    for (int j = tid; j < deg; j += 64)
        ew[j] = __expf(ew[j] - sm) * ss;
    __syncthreads();

    if (tid < C2) {
        float acc = 0.f;
        for (int j = 0; j < deg; j++)
            acc += ew[j] * g_h2[(size_t)snbr[j] * C2 + tid];
        out[(size_t)i * C2 + tid] = acc;
    }
}

// ---------------------------------------------------------------------------
extern "C" void kernel_launch(void* const* d_in, const int* in_sizes, int n_in,
                              void* d_out, int out_size)
{
    const float* x      = (const float*)d_in[0];
    const void*  adj    = d_in[1];
    const float* W1     = (const float*)d_in[2];
    const float* a1_src = (const float*)d_in[3];
    const float* a1_dst = (const float*)d_in[4];
    const float* W2     = (const float*)d_in[5];
    const float* a2_src = (const float*)d_in[6];
    const float* a2_dst = (const float*)d_in[7];
    float* out = (float*)d_out;

    k_build_nbr<<<N_NODES, 128>>>(adj);
    k_gemm1<<<N_NODES / 64, 256>>>(x, W1);
    k_scores1<<<(N_NODES * NH1 + 255) / 256, 256>>>(a1_src, a1_dst);
    k_attn1<<<N_NODES, 128>>>();
    k_gemm2<<<N_NODES / 16, 256>>>(W2);
    k_scores2<<<(N_NODES + 255) / 256, 256>>>(a2_src, a2_dst);
    k_attn2<<<N_NODES, 64>>>(out);
}

// round 2
// speedup vs baseline: 2.9691x; 2.9691x over previous
#include <cuda_runtime.h>
#include <cstdint>

// ---------------------------------------------------------------------------
// GAT, 2 layers. N=4096, F=512, H1=8, D1=8 (64 hidden), C=16.
// ---------------------------------------------------------------------------

#define N_NODES 4096
#define F_IN    512
#define HD1     64
#define NH1     8
#define D1      8
#define C2      16
#define MAXDEG  256

__device__ int   g_nbr[N_NODES * MAXDEG];
__device__ int   g_deg[N_NODES];
__device__ float g_h1 [N_NODES * HD1];
__device__ float g_es1[N_NODES * NH1];
__device__ float g_ed1[N_NODES * NH1];
__device__ float g_a1 [N_NODES * HD1];
__device__ float g_h2 [N_NODES * C2];
__device__ float g_es2[N_NODES];
__device__ float g_ed2[N_NODES];

// ---------------------------------------------------------------------------
// K1: neighbor lists. 1 block/row, 128 thr. Coalesced vector loads (4 cols
// per thread per round, 8 rounds) + shfl warp scan for ordered compaction.
// ---------------------------------------------------------------------------
__global__ __launch_bounds__(128) void k_build_nbr(const void* __restrict__ adj)
{
    const int i    = blockIdx.x;
    const int tid  = threadIdx.x;
    const int lane = tid & 31;
    const int wid  = tid >> 5;
    const uint8_t* u8 = (const uint8_t*)adj;

    // layout via self-loop adj[1][1]==1 : bool8 / int32 / float32
    int fmt;
    if (u8[(size_t)N_NODES + 1] == 1)            fmt = 0;
    else if (u8[4 * ((size_t)N_NODES + 1)] == 1) fmt = 1;
    else                                         fmt = 2;

    __shared__ int wt[2][4];
    int* out = g_nbr + (size_t)i * MAXDEG;
    int run = 0;   // identical across all threads

    #pragma unroll 1
    for (int r = 0; r < 8; r++) {
        const int cbase = (r * 128 + tid) * 4;
        int p0, p1, p2, p3;
        if (fmt == 0) {
            uint32_t w = *(const uint32_t*)(u8 + (size_t)i * N_NODES + cbase);
            p0 = (w & 0x000000FFu) != 0;
            p1 = (w & 0x0000FF00u) != 0;
            p2 = (w & 0x00FF0000u) != 0;
            p3 = (w & 0xFF000000u) != 0;
        } else if (fmt == 1) {
            int4 v = *(const int4*)((const int*)adj + (size_t)i * N_NODES + cbase);
            p0 = v.x != 0; p1 = v.y != 0; p2 = v.z != 0; p3 = v.w != 0;
        } else {
            float4 v = *(const float4*)((const float*)adj + (size_t)i * N_NODES + cbase);
            p0 = v.x != 0.f; p1 = v.y != 0.f; p2 = v.z != 0.f; p3 = v.w != 0.f;
        }
        int cnt = p0 + p1 + p2 + p3;

        // inclusive warp scan
        int incl = cnt;
        #pragma unroll
        for (int o = 1; o < 32; o <<= 1) {
            int t = __shfl_up_sync(0xFFFFFFFFu, incl, o);
            if (lane >= o) incl += t;
        }
        if (lane == 31) wt[r & 1][wid] = incl;
        __syncthreads();

        int wpre = 0, btot = 0;
        #pragma unroll
        for (int wq = 0; wq < 4; wq++) {
            int t = wt[r & 1][wq];
            if (wq < wid) wpre += t;
            btot += t;
        }
        int base = run + wpre + (incl - cnt);
        if (p0) { if (base < MAXDEG) out[base] = cbase + 0; base++; }
        if (p1) { if (base < MAXDEG) out[base] = cbase + 1; base++; }
        if (p2) { if (base < MAXDEG) out[base] = cbase + 2; base++; }
        if (p3) { if (base < MAXDEG) out[base] = cbase + 3; base++; }
        run += btot;
    }
    if (tid == 0) g_deg[i] = (run > MAXDEG) ? MAXDEG : run;
}

// ---------------------------------------------------------------------------
// K2: GEMM1 h1 = x @ W1 (4096x512 * 512x64), M-tile 32 -> 128 blocks.
// Fused epilogue: es1/ed1 via shfl pair-reduction.
// ---------------------------------------------------------------------------
__global__ __launch_bounds__(256) void k_gemm1(const float* __restrict__ X,
                                               const float* __restrict__ W,
                                               const float* __restrict__ a_src,
                                               const float* __restrict__ a_dst)
{
    __shared__ float As[32][33];   // [k][m], pad 33 => conflict-free transpose store
    __shared__ float Bs[32][64];   // [k][n]

    const int tid = threadIdx.x;
    const int tx  = tid & 15;      // n group: cols tx*4..tx*4+3
    const int ty  = tid >> 4;      // m group: rows ty*2, ty*2+1
    const int m0  = blockIdx.x * 32;

    float acc[2][4] = {};

    for (int kt = 0; kt < F_IN; kt += 32) {
        {   // A: 32 rows x 32 cols = 256 float4 (one per thread), transposed store
            int r  = tid >> 3;
            int c4 = tid & 7;
            float4 v = *(const float4*)(X + (size_t)(m0 + r) * F_IN + kt + c4 * 4);
            As[c4 * 4 + 0][r] = v.x;
            As[c4 * 4 + 1][r] = v.y;
            As[c4 * 4 + 2][r] = v.z;
            As[c4 * 4 + 3][r] = v.w;
        }
        #pragma unroll
        for (int it = 0; it < 2; it++) {   // B: 32x64 = 512 float4
            int id = tid + it * 256;
            int r  = id >> 4;
            int c4 = id & 15;
            *(float4*)(&Bs[r][c4 * 4]) =
                *(const float4*)(W + (size_t)(kt + r) * HD1 + c4 * 4);
        }
        __syncthreads();
        #pragma unroll
        for (int k = 0; k < 32; k++) {
            float a0 = As[k][ty * 2 + 0];
            float a1 = As[k][ty * 2 + 1];
            float4 b = *(const float4*)(&Bs[k][tx * 4]);
            acc[0][0] += a0 * b.x; acc[0][1] += a0 * b.y;
            acc[0][2] += a0 * b.z; acc[0][3] += a0 * b.w;
            acc[1][0] += a1 * b.x; acc[1][1] += a1 * b.y;
            acc[1][2] += a1 * b.z; acc[1][3] += a1 * b.w;
        }
        __syncthreads();
    }

    // write h1
    #pragma unroll
    for (int u = 0; u < 2; u++) {
        float4 v = make_float4(acc[u][0], acc[u][1], acc[u][2], acc[u][3]);
        *(float4*)(g_h1 + (size_t)(m0 + ty * 2 + u) * HD1 + tx * 4) = v;
    }

    // fused scores: head h = tx/2; this thread's 4 cols lie in one head.
    float4 ws = *(const float4*)(a_src + tx * 4);
    float4 wd = *(const float4*)(a_dst + tx * 4);
    float s0 = acc[0][0]*ws.x + acc[0][1]*ws.y + acc[0][2]*ws.z + acc[0][3]*ws.w;
    float s1 = acc[1][0]*ws.x + acc[1][1]*ws.y + acc[1][2]*ws.z + acc[1][3]*ws.w;
    float d0 = acc[0][0]*wd.x + acc[0][1]*wd.y + acc[0][2]*wd.z + acc[0][3]*wd.w;
    float d1 = acc[1][0]*wd.x + acc[1][1]*wd.y + acc[1][2]*wd.z + acc[1][3]*wd.w;
    // partner lane = lane^1 (same ty, tx^1)
    s0 += __shfl_xor_sync(0xFFFFFFFFu, s0, 1);
    s1 += __shfl_xor_sync(0xFFFFFFFFu, s1, 1);
    d0 += __shfl_xor_sync(0xFFFFFFFFu, d0, 1);
    d1 += __shfl_xor_sync(0xFFFFFFFFu, d1, 1);
    if ((tx & 1) == 0) {
        int h = tx >> 1;
        g_es1[(m0 + ty * 2 + 0) * NH1 + h] = s0;
        g_es1[(m0 + ty * 2 + 1) * NH1 + h] = s1;
        g_ed1[(m0 + ty * 2 + 0) * NH1 + h] = d0;
        g_ed1[(m0 + ty * 2 + 1) * NH1 + h] = d1;
    }
}

// ---------------------------------------------------------------------------
// K3: layer-1 sparse attention + ELU. 1 block/row, 128 threads.
// ---------------------------------------------------------------------------
__global__ __launch_bounds__(128) void k_attn1()
{
    const int i   = blockIdx.x;
    const int tid = threadIdx.x;
    const int deg = g_deg[i];

    __shared__ int   snbr[MAXDEG];
    __shared__ float ew[MAXDEG * NH1];
    __shared__ float sm[NH1], ss[NH1];

    for (int j = tid; j < deg; j += 128)
        snbr[j] = g_nbr[(size_t)i * MAXDEG + j];
    __syncthreads();

    const int tot = deg * NH1;
    for (int idx = tid; idx < tot; idx += 128) {
        int j = idx >> 3, h = idx & 7;
        float e = g_es1[i * NH1 + h] + g_ed1[snbr[j] * NH1 + h];
        e = (e > 0.f) ? e : 0.2f * e;
        ew[idx] = e;
    }
    __syncthreads();

    if (tid < NH1) {
        float m = -1e30f;
        for (int j = 0; j < deg; j++) m = fmaxf(m, ew[j * NH1 + tid]);
        float s = 0.f;
        for (int j = 0; j < deg; j++) s += __expf(ew[j * NH1 + tid] - m);
        sm[tid] = m;
        ss[tid] = 1.f / s;
    }
    __syncthreads();

    for (int idx = tid; idx < tot; idx += 128) {
        int h = idx & 7;
        ew[idx] = __expf(ew[idx] - sm[h]) * ss[h];
    }
    __syncthreads();

    if (tid < HD1) {
        const int h = tid >> 3;
        float a0 = 0.f, a1 = 0.f, a2 = 0.f, a3 = 0.f;
        int j = 0;
        for (; j + 4 <= deg; j += 4) {
            a0 += ew[(j+0) * NH1 + h] * g_h1[(size_t)snbr[j+0] * HD1 + tid];
            a1 += ew[(j+1) * NH1 + h] * g_h1[(size_t)snbr[j+1] * HD1 + tid];
            a2 += ew[(j+2) * NH1 + h] * g_h1[(size_t)snbr[j+2] * HD1 + tid];
            a3 += ew[(j+3) * NH1 + h] * g_h1[(size_t)snbr[j+3] * HD1 + tid];
        }
        for (; j < deg; j++)
            a0 += ew[j * NH1 + h] * g_h1[(size_t)snbr[j] * HD1 + tid];
        float acc = (a0 + a1) + (a2 + a3);
        acc = (acc > 0.f) ? acc : expm1f(acc);   // ELU
        g_a1[(size_t)i * HD1 + tid] = acc;
    }
}

// ---------------------------------------------------------------------------
// K4: GEMM2 h2 = a1 @ W2 (4096x64 * 64x16) + fused es2/ed2 (16-lane shfl).
// ---------------------------------------------------------------------------
__global__ __launch_bounds__(256) void k_gemm2(const float* __restrict__ W2,
                                               const float* __restrict__ a_src,
                                               const float* __restrict__ a_dst)
{
    __shared__ float sW[HD1 * C2];   // 1024
    __shared__ float sA[16 * HD1];   // 16 rows x 64

    const int tid = threadIdx.x;
    const int n0  = blockIdx.x * 16;

    *(float4*)(&sW[tid * 4]) = *(const float4*)(W2 + tid * 4);
    {
        int r  = tid >> 4;
        int c4 = tid & 15;
        *(float4*)(&sA[r * HD1 + c4 * 4]) =
            *(const float4*)(g_a1 + (size_t)(n0 + r) * HD1 + c4 * 4);
    }
    __syncthreads();

    const int rloc = tid >> 4;
    const int c    = tid & 15;
    float acc = 0.f;
    #pragma unroll
    for (int k = 0; k < HD1; k++)
        acc += sA[rloc * HD1 + k] * sW[k * C2 + c];
    g_h2[(size_t)(n0 + rloc) * C2 + c] = acc;

    // fused scores: reduce over 16 lanes (c dimension)
    float s = acc * a_src[c];
    float d = acc * a_dst[c];
    #pragma unroll
    for (int o = 8; o >= 1; o >>= 1) {
        s += __shfl_xor_sync(0xFFFFFFFFu, s, o);
        d += __shfl_xor_sync(0xFFFFFFFFu, d, o);
    }
    if (c == 0) {
        g_es2[n0 + rloc] = s;
        g_ed2[n0 + rloc] = d;
    }
}

// ---------------------------------------------------------------------------
// K5: layer-2 sparse attention. 1 block/row, 64 threads.
// ---------------------------------------------------------------------------
__global__ __launch_bounds__(64) void k_attn2(float* __restrict__ out)
{
    const int i   = blockIdx.x;
    const int tid = threadIdx.x;
    const int deg = g_deg[i];

    __shared__ int   snbr[MAXDEG];
    __shared__ float ew[MAXDEG];
    __shared__ float sm, ss;

    for (int j = tid; j < deg; j += 64)
        snbr[j] = g_nbr[(size_t)i * MAXDEG + j];
    __syncthreads();

    const float esi = g_es2[i];
    for (int j = tid; j < deg; j += 64) {
        float e = esi + g_ed2[snbr[j]];
        e = (e > 0.f) ? e : 0.2f * e;
        ew[j] = e;
    }
    __syncthreads();

    if (tid == 0) {
        float m = -1e30f;
        for (int j = 0; j < deg; j++) m = fmaxf(m, ew[j]);
        float s = 0.f;
        for (int j = 0; j < deg; j++) s += __expf(ew[j] - m);
        sm = m;
        ss = 1.f / s;
    }
    __syncthreads();

    for (int j = tid; j < deg; j += 64)
        ew[j] = __expf(ew[j] - sm) * ss;
    __syncthreads();

    if (tid < C2) {
        float a0 = 0.f, a1 = 0.f, a2 = 0.f, a3 = 0.f;
        int j = 0;
        for (; j + 4 <= deg; j += 4) {
            a0 += ew[j+0] * g_h2[(size_t)snbr[j+0] * C2 + tid];
            a1 += ew[j+1] * g_h2[(size_t)snbr[j+1] * C2 + tid];
            a2 += ew[j+2] * g_h2[(size_t)snbr[j+2] * C2 + tid];
            a3 += ew[j+3] * g_h2[(size_t)snbr[j+3] * C2 + tid];
        }
        for (; j < deg; j++)
            a0 += ew[j] * g_h2[(size_t)snbr[j] * C2 + tid];
        out[(size_t)i * C2 + tid] = (a0 + a1) + (a2 + a3);
    }
}

// ---------------------------------------------------------------------------
extern "C" void kernel_launch(void* const* d_in, const int* in_sizes, int n_in,
                              void* d_out, int out_size)
{
    const float* x      = (const float*)d_in[0];
    const void*  adj    = d_in[1];
    const float* W1     = (const float*)d_in[2];
    const float* a1_src = (const float*)d_in[3];
    const float* a1_dst = (const float*)d_in[4];
    const float* W2     = (const float*)d_in[5];
    const float* a2_src = (const float*)d_in[6];
    const float* a2_dst = (const float*)d_in[7];
    float* out = (float*)d_out;

    k_build_nbr<<<N_NODES, 128>>>(adj);
    k_gemm1<<<N_NODES / 32, 256>>>(x, W1, a1_src, a1_dst);
    k_attn1<<<N_NODES, 128>>>();
    k_gemm2<<<N_NODES / 16, 256>>>(W2, a2_src, a2_dst);
    k_attn2<<<N_NODES, 64>>>(out);
}

// round 3
// speedup vs baseline: 3.5041x; 1.1802x over previous
#include <cuda_runtime.h>
#include <cstdint>

// ---------------------------------------------------------------------------
// GAT, 2 layers. N=4096, F=512, H1=8, D1=8 (64 hidden), C=16.
// ---------------------------------------------------------------------------

#define N_NODES 4096
#define F_IN    512
#define HD1     64
#define NH1     8
#define D1      8
#define C2      16
#define MAXDEG  256

__device__ int   g_nbr[N_NODES * MAXDEG];
__device__ int   g_deg[N_NODES];
__device__ float g_h1 [N_NODES * HD1];
__device__ float g_es1[N_NODES * NH1];
__device__ float g_ed1[N_NODES * NH1];
__device__ float g_h2 [N_NODES * C2];
__device__ float g_es2[N_NODES];
__device__ float g_ed2[N_NODES];

// ---------------------------------------------------------------------------
// K1: neighbor lists. 1 block/row, 128 thr. All loads first (MLP=8) into a
// 32-bit predicate mask, ONE block scan, then emit. Single __syncthreads.
// ---------------------------------------------------------------------------
__global__ __launch_bounds__(128) void k_build_nbr(const void* __restrict__ adj)
{
    const int i    = blockIdx.x;
    const int tid  = threadIdx.x;
    const int lane = tid & 31;
    const int wid  = tid >> 5;
    const uint8_t* u8 = (const uint8_t*)adj;

    // layout via self-loop adj[1][1]==1 : bool8 / int32 / float32
    int fmt;
    if (u8[(size_t)N_NODES + 1] == 1)            fmt = 0;
    else if (u8[4 * ((size_t)N_NODES + 1)] == 1) fmt = 1;
    else                                         fmt = 2;

    uint32_t mask = 0;
    #pragma unroll
    for (int r = 0; r < 8; r++) {
        const int cbase = (r * 128 + tid) * 4;
        uint32_t p0, p1, p2, p3;
        if (fmt == 0) {
            uint32_t w = *(const uint32_t*)(u8 + (size_t)i * N_NODES + cbase);
            p0 = (w & 0x000000FFu) != 0;
            p1 = (w & 0x0000FF00u) != 0;
            p2 = (w & 0x00FF0000u) != 0;
            p3 = (w & 0xFF000000u) != 0;
        } else if (fmt == 1) {
            int4 v = *(const int4*)((const int*)adj + (size_t)i * N_NODES + cbase);
            p0 = v.x != 0; p1 = v.y != 0; p2 = v.z != 0; p3 = v.w != 0;
        } else {
            float4 v = *(const float4*)((const float*)adj + (size_t)i * N_NODES + cbase);
            p0 = v.x != 0.f; p1 = v.y != 0.f; p2 = v.z != 0.f; p3 = v.w != 0.f;
        }
        mask |= (p0 << (r * 4)) | (p1 << (r * 4 + 1)) |
                (p2 << (r * 4 + 2)) | (p3 << (r * 4 + 3));
    }

    const int cnt = __popc(mask);

    // block scan: warp inclusive scan + cross-warp offsets (one sync)
    int incl = cnt;
    #pragma unroll
    for (int o = 1; o < 32; o <<= 1) {
        int t = __shfl_up_sync(0xFFFFFFFFu, incl, o);
        if (lane >= o) incl += t;
    }
    __shared__ int wsum[4];
    if (lane == 31) wsum[wid] = incl;
    __syncthreads();
    int wpre = 0, total = 0;
    #pragma unroll
    for (int wq = 0; wq < 4; wq++) {
        int t = wsum[wq];
        if (wq < wid) wpre += t;
        total += t;
    }
    if (tid == 0) g_deg[i] = (total > MAXDEG) ? MAXDEG : total;

    int base = wpre + (incl - cnt);
    int* out = g_nbr + (size_t)i * MAXDEG;
    #pragma unroll
    for (int r = 0; r < 8; r++) {
        const int cbase = (r * 128 + tid) * 4;
        #pragma unroll
        for (int q = 0; q < 4; q++) {
            if ((mask >> (r * 4 + q)) & 1u) {
                if (base < MAXDEG) out[base] = cbase + q;
                base++;
            }
        }
    }
}

// ---------------------------------------------------------------------------
// K2: GEMM1 h1 = x @ W1 (4096x512 * 512x64), M-tile 32 -> 128 blocks.
// Fused epilogue: es1/ed1 via shfl pair-reduction.
// ---------------------------------------------------------------------------
__global__ __launch_bounds__(256) void k_gemm1(const float* __restrict__ X,
                                               const float* __restrict__ W,
                                               const float* __restrict__ a_src,
                                               const float* __restrict__ a_dst)
{
    __shared__ float As[32][33];   // [k][m]
    __shared__ float Bs[32][64];   // [k][n]

    const int tid = threadIdx.x;
    const int tx  = tid & 15;
    const int ty  = tid >> 4;
    const int m0  = blockIdx.x * 32;

    float acc[2][4] = {};

    for (int kt = 0; kt < F_IN; kt += 32) {
        {
            int r  = tid >> 3;
            int c4 = tid & 7;
            float4 v = *(const float4*)(X + (size_t)(m0 + r) * F_IN + kt + c4 * 4);
            As[c4 * 4 + 0][r] = v.x;
            As[c4 * 4 + 1][r] = v.y;
            As[c4 * 4 + 2][r] = v.z;
            As[c4 * 4 + 3][r] = v.w;
        }
        #pragma unroll
        for (int it = 0; it < 2; it++) {
            int id = tid + it * 256;
            int r  = id >> 4;
            int c4 = id & 15;
            *(float4*)(&Bs[r][c4 * 4]) =
                *(const float4*)(W + (size_t)(kt + r) * HD1 + c4 * 4);
        }
        __syncthreads();
        #pragma unroll
        for (int k = 0; k < 32; k++) {
            float a0 = As[k][ty * 2 + 0];
            float a1 = As[k][ty * 2 + 1];
            float4 b = *(const float4*)(&Bs[k][tx * 4]);
            acc[0][0] += a0 * b.x; acc[0][1] += a0 * b.y;
            acc[0][2] += a0 * b.z; acc[0][3] += a0 * b.w;
            acc[1][0] += a1 * b.x; acc[1][1] += a1 * b.y;
            acc[1][2] += a1 * b.z; acc[1][3] += a1 * b.w;
        }
        __syncthreads();
    }

    #pragma unroll
    for (int u = 0; u < 2; u++) {
        float4 v = make_float4(acc[u][0], acc[u][1], acc[u][2], acc[u][3]);
        *(float4*)(g_h1 + (size_t)(m0 + ty * 2 + u) * HD1 + tx * 4) = v;
    }

    float4 ws = *(const float4*)(a_src + tx * 4);
    float4 wd = *(const float4*)(a_dst + tx * 4);
    float s0 = acc[0][0]*ws.x + acc[0][1]*ws.y + acc[0][2]*ws.z + acc[0][3]*ws.w;
    float s1 = acc[1][0]*ws.x + acc[1][1]*ws.y + acc[1][2]*ws.z + acc[1][3]*ws.w;
    float d0 = acc[0][0]*wd.x + acc[0][1]*wd.y + acc[0][2]*wd.z + acc[0][3]*wd.w;
    float d1 = acc[1][0]*wd.x + acc[1][1]*wd.y + acc[1][2]*wd.z + acc[1][3]*wd.w;
    s0 += __shfl_xor_sync(0xFFFFFFFFu, s0, 1);
    s1 += __shfl_xor_sync(0xFFFFFFFFu, s1, 1);
    d0 += __shfl_xor_sync(0xFFFFFFFFu, d0, 1);
    d1 += __shfl_xor_sync(0xFFFFFFFFu, d1, 1);
    if ((tx & 1) == 0) {
        int h = tx >> 1;
        g_es1[(m0 + ty * 2 + 0) * NH1 + h] = s0;
        g_es1[(m0 + ty * 2 + 1) * NH1 + h] = s1;
        g_ed1[(m0 + ty * 2 + 0) * NH1 + h] = d0;
        g_ed1[(m0 + ty * 2 + 1) * NH1 + h] = d1;
    }
}

// ---------------------------------------------------------------------------
// K3: layer-1 attention + ELU + FUSED layer-2 projection & scores.
// 1 block/row, 64 threads.
// ---------------------------------------------------------------------------
__global__ __launch_bounds__(64) void k_attn1(const float* __restrict__ W2,
                                              const float* __restrict__ a2_src,
                                              const float* __restrict__ a2_dst)
{
    const int i   = blockIdx.x;
    const int tid = threadIdx.x;
    const int deg = g_deg[i];

    __shared__ int   snbr[MAXDEG];
    __shared__ float ew[MAXDEG * NH1];
    __shared__ float sm[NH1], ss[NH1], sesi[NH1];
    __shared__ float sa1[HD1];

    for (int j = tid; j < deg; j += 64)
        snbr[j] = g_nbr[(size_t)i * MAXDEG + j];
    if (tid < NH1) sesi[tid] = g_es1[i * NH1 + tid];
    __syncthreads();

    const int tot = deg * NH1;
    for (int idx = tid; idx < tot; idx += 64) {
        int j = idx >> 3, h = idx & 7;
        float e = sesi[h] + g_ed1[snbr[j] * NH1 + h];
        e = (e > 0.f) ? e : 0.2f * e;
        ew[idx] = e;
    }
    __syncthreads();

    if (tid < NH1) {
        float m = -1e30f;
        for (int j = 0; j < deg; j++) m = fmaxf(m, ew[j * NH1 + tid]);
        float s = 0.f;
        for (int j = 0; j < deg; j++) s += __expf(ew[j * NH1 + tid] - m);
        sm[tid] = m;
        ss[tid] = 1.f / s;
    }
    __syncthreads();

    for (int idx = tid; idx < tot; idx += 64) {
        int h = idx & 7;
        ew[idx] = __expf(ew[idx] - sm[h]) * ss[h];
    }
    __syncthreads();

    // gather (col = tid), ELU, stash a1 in smem
    {
        const int h = tid >> 3;
        float a0 = 0.f, a1 = 0.f, a2 = 0.f, a3 = 0.f;
        int j = 0;
        for (; j + 4 <= deg; j += 4) {
            a0 += ew[(j+0) * NH1 + h] * g_h1[(size_t)snbr[j+0] * HD1 + tid];
            a1 += ew[(j+1) * NH1 + h] * g_h1[(size_t)snbr[j+1] * HD1 + tid];
            a2 += ew[(j+2) * NH1 + h] * g_h1[(size_t)snbr[j+2] * HD1 + tid];
            a3 += ew[(j+3) * NH1 + h] * g_h1[(size_t)snbr[j+3] * HD1 + tid];
        }
        for (; j < deg; j++)
            a0 += ew[j * NH1 + h] * g_h1[(size_t)snbr[j] * HD1 + tid];
        float acc = (a0 + a1) + (a2 + a3);
        acc = (acc > 0.f) ? acc : expm1f(acc);   // ELU
        sa1[tid] = acc;
    }
    __syncthreads();

    // fused GEMM2 row: h2[i,:] = sa1 @ W2 (64x16), + es2/ed2 scores
    if (tid < C2) {
        float v = 0.f;
        #pragma unroll 8
        for (int k = 0; k < HD1; k++)
            v += sa1[k] * __ldg(&W2[k * C2 + tid]);
        g_h2[(size_t)i * C2 + tid] = v;

        float s = v * a2_src[tid];
        float d = v * a2_dst[tid];
        #pragma unroll
        for (int o = 8; o >= 1; o >>= 1) {
            s += __shfl_xor_sync(0x0000FFFFu, s, o);
            d += __shfl_xor_sync(0x0000FFFFu, d, o);
        }
        if (tid == 0) {
            g_es2[i] = s;
            g_ed2[i] = d;
        }
    }
}

// ---------------------------------------------------------------------------
// K4: layer-2 sparse attention. 1 warp per row, warp-sync only.
// ---------------------------------------------------------------------------
__global__ __launch_bounds__(32) void k_attn2(float* __restrict__ out)
{
    const int i    = blockIdx.x;
    const int lane = threadIdx.x;
    const int deg  = g_deg[i];

    __shared__ int   snbr[MAXDEG];
    __shared__ float ew[MAXDEG];

    for (int j = lane; j < deg; j += 32)
        snbr[j] = g_nbr[(size_t)i * MAXDEG + j];
    __syncwarp();

    const float esi = g_es2[i];
    float mloc = -1e30f;
    for (int j = lane; j < deg; j += 32) {
        float e = esi + g_ed2[snbr[j]];
        e = (e > 0.f) ? e : 0.2f * e;
        ew[j] = e;
        mloc = fmaxf(mloc, e);
    }
    #pragma unroll
    for (int o = 16; o >= 1; o >>= 1)
        mloc = fmaxf(mloc, __shfl_xor_sync(0xFFFFFFFFu, mloc, o));
    __syncwarp();

    float sloc = 0.f;
    for (int j = lane; j < deg; j += 32) {
        float w = __expf(ew[j] - mloc);
        ew[j] = w;
        sloc += w;
    }
    #pragma unroll
    for (int o = 16; o >= 1; o >>= 1)
        sloc += __shfl_xor_sync(0xFFFFFFFFu, sloc, o);
    const float inv = 1.f / sloc;
    __syncwarp();

    if (lane < C2) {
        float a0 = 0.f, a1 = 0.f, a2 = 0.f, a3 = 0.f;
        int j = 0;
        for (; j + 4 <= deg; j += 4) {
            a0 += ew[j+0] * g_h2[(size_t)snbr[j+0] * C2 + lane];
            a1 += ew[j+1] * g_h2[(size_t)snbr[j+1] * C2 + lane];
            a2 += ew[j+2] * g_h2[(size_t)snbr[j+2] * C2 + lane];
            a3 += ew[j+3] * g_h2[(size_t)snbr[j+3] * C2 + lane];
        }
        for (; j < deg; j++)
            a0 += ew[j] * g_h2[(size_t)snbr[j] * C2 + lane];
        out[(size_t)i * C2 + lane] = ((a0 + a1) + (a2 + a3)) * inv;
    }
}

// ---------------------------------------------------------------------------
extern "C" void kernel_launch(void* const* d_in, const int* in_sizes, int n_in,
                              void* d_out, int out_size)
{
    const float* x      = (const float*)d_in[0];
    const void*  adj    = d_in[1];
    const float* W1     = (const float*)d_in[2];
    const float* a1_src = (const float*)d_in[3];
    const float* a1_dst = (const float*)d_in[4];
    const float* W2     = (const float*)d_in[5];
    const float* a2_src = (const float*)d_in[6];
    const float* a2_dst = (const float*)d_in[7];
    float* out = (float*)d_out;

    k_build_nbr<<<N_NODES, 128>>>(adj);
    k_gemm1<<<N_NODES / 32, 256>>>(x, W1, a1_src, a1_dst);
    k_attn1<<<N_NODES, 64>>>(W2, a2_src, a2_dst);
    k_attn2<<<N_NODES, 32>>>(out);
}